// round 5
// baseline (speedup 1.0000x reference)
#include <cuda_runtime.h>
#include <math.h>
#include <stdint.h>

#define BSZ   16384
#define LSP   32
#define C1    128
#define C2    64
#define CH2   16

// ---- persistent device scratch ----
__device__ float  g_images[BSZ * LSP];
__device__ float  g_h2[BSZ * C2 * LSP];
__device__ double g_stats1[2 * C1];
__device__ double g_stats2[2 * C2];
__device__ float  g_a1[C1], g_c1[C1];
__device__ float  g_a2[C2], g_c2[C2];

__device__ __forceinline__ uint32_t f2tf32(float x) {
    uint32_t r;
    asm("cvt.rna.tf32.f32 %0, %1;" : "=r"(r) : "f"(x));
    return r;
}

// ================================================================
__global__ void k_zero_stats() {
    int t = threadIdx.x;
    if (t < 2 * C1) g_stats1[t] = 0.0;
    if (t < 2 * C2) g_stats2[t] = 0.0;
}

// ------------------------------------------------------------------
// given = probs[:8]/max(probs[:8]) (sum-normalization cancels).
__global__ void k_images(const float* __restrict__ x, const float* __restrict__ qp) {
    int t = blockIdx.x * blockDim.x + threadIdx.x;
    if (t >= BSZ * 4) return;
    int b = t >> 2, g = t & 3;
    float c[4], s[4];
#pragma unroll
    for (int q = 0; q < 4; q++) {
        float th = 0.5f * (x[b * 4 + q] + qp[g * 4 + q]);
        c[q] = cosf(th);
        s[q] = sinf(th);
    }
    float p[8];
    float mx = 0.f;
#pragma unroll
    for (int i = 0; i < 8; i++) {
        float a = c[0];
        a *= ((i >> 2) & 1) ? s[1] : c[1];
        a *= ((i >> 1) & 1) ? s[2] : c[2];
        a *= (i & 1)        ? s[3] : c[3];
        float pp = a * a;
        p[i] = pp;
        mx = fmaxf(mx, pp);
    }
    float inv = 1.0f / mx;
#pragma unroll
    for (int i = 0; i < 8; i++) g_images[b * 32 + g * 8 + i] = p[i] * inv;
}

// ------------------------------------------------------------------
__global__ void k_conv1_stats(const float* __restrict__ w1, const float* __restrict__ b1) {
    __shared__ float sh[CH2][34];
    int tid = threadIdx.x;
    int b0 = blockIdx.x * CH2;
    for (int i = tid; i < CH2 * 32; i += 128)
        sh[i >> 5][(i & 31) + 1] = g_images[(b0 + (i >> 5)) * 32 + (i & 31)];
    if (tid < CH2) { sh[tid][0] = 0.f; sh[tid][33] = 0.f; }
    __syncthreads();

    int oc = tid;
    float wA = w1[oc * 3 + 2], wB = w1[oc * 3 + 1], wC = w1[oc * 3 + 0], bb = b1[oc];
    float sum = 0.f, sq = 0.f;
    for (int r = 0; r < CH2; r++) {
#pragma unroll
        for (int p = 0; p < 32; p++) {
            float y = bb + sh[r][p] * wA + sh[r][p + 1] * wB + sh[r][p + 2] * wC;
            y = fmaxf(y, 0.f);
            sum += y;
            sq += y * y;
        }
    }
    atomicAdd(&g_stats1[oc], (double)sum);
    atomicAdd(&g_stats1[C1 + oc], (double)sq);
}

// ------------------------------------------------------------------
__global__ void k_fin1(const float* __restrict__ gamma, const float* __restrict__ beta) {
    int c = threadIdx.x;
    if (c >= C1) return;
    double N = (double)BSZ * LSP;
    double mean = g_stats1[c] / N;
    double var = g_stats1[C1 + c] / N - mean * mean;
    float a = gamma[c] * (float)(1.0 / sqrt(var + 1e-5));
    g_a1[c] = a;
    g_c1[c] = beta[c] - (float)mean * a;
}

__global__ void k_fin2(const float* __restrict__ gamma, const float* __restrict__ beta) {
    int c = threadIdx.x;
    if (c >= C2) return;
    double N = (double)BSZ * LSP;
    double mean = g_stats2[c] / N;
    double var = g_stats2[C2 + c] / N - mean * mean;
    float a = gamma[c] * (float)(1.0 / sqrt(var + 1e-5));
    g_a2[c] = a;
    g_c2[c] = beta[c] - (float)mean * a;
}

// ------------------------------------------------------------------
// conv2 via mma.sync tf32 (m16n8k8) with 3xTF32 split for fp32-grade accuracy.
// D = Ahi*Bhi + Alo*Bhi + Ahi*Blo  (lo*lo dropped, ~2^-22 relative).
// Per CTA: 4 batch rows -> M=128 pos, N=64 oc, K=384 (3 taps x 128 ic).
#define OFF_H1H   0                    // 4*128*40 = 20480
#define OFF_H1L   20480                // 20480
#define OFF_SBH   40960                // 64*72 = 4608
#define OFF_SBL   45568                // 4608
#define OFF_SP    50176                // 128*6
#define OFF_SIMG  50944                // 4*34
#define OFF_RED   51080                // 128
#define SM_FLOATS 51208                // 204832 bytes

__global__ void __launch_bounds__(256, 1)
k_conv2(const float* __restrict__ w1, const float* __restrict__ b1,
        const float* __restrict__ w2, const float* __restrict__ b2) {
    extern __shared__ float sm[];
    uint32_t* shH = (uint32_t*)(sm + OFF_H1H);
    uint32_t* shL = (uint32_t*)(sm + OFF_H1L);
    uint32_t* sBH = (uint32_t*)(sm + OFF_SBH);
    uint32_t* sBL = (uint32_t*)(sm + OFF_SBL);
    float* sp   = sm + OFF_SP;
    float* simg = sm + OFF_SIMG;
    float* red  = sm + OFF_RED;

    int tid = threadIdx.x;
    int wid = tid >> 5, lid = tid & 31;
    int g = lid >> 2, q = lid & 3;
    int bbase = blockIdx.x * 4;

    if (tid < 128) red[tid] = 0.f;
    for (int i = tid; i < 128; i += 256) {
        sp[i * 6 + 0] = w1[i * 3 + 0];
        sp[i * 6 + 1] = w1[i * 3 + 1];
        sp[i * 6 + 2] = w1[i * 3 + 2];
        sp[i * 6 + 3] = b1[i];
        sp[i * 6 + 4] = g_a1[i];
        sp[i * 6 + 5] = g_c1[i];
    }
    for (int i = tid; i < 4 * 32; i += 256) {
        int bl = i >> 5, p = i & 31;
        simg[bl * 34 + p + 1] = g_images[(bbase + bl) * 32 + p];
    }
    if (tid < 4) { simg[tid * 34] = 0.f; simg[tid * 34 + 33] = 0.f; }
    __syncthreads();

    // --- h1n split into tf32 hi/lo, [bl][ic][q0=0..33] halo-padded, stride 40 ---
    for (int idx = tid; idx < 4 * 128 * 34; idx += 256) {
        int bl = idx / 4352, r = idx - bl * 4352;
        int ic = r / 34, q0 = r - ic * 34;
        float v = 0.f;
        if (q0 >= 1 && q0 <= 32) {
            int p = q0 - 1;
            const float* pp = &sp[ic * 6];
            float y = pp[3] + simg[bl * 34 + p] * pp[2]
                            + simg[bl * 34 + p + 1] * pp[1]
                            + simg[bl * 34 + p + 2] * pp[0];
            y = fmaxf(y, 0.f);
            v = fmaf(pp[4], y, pp[5]);
        }
        uint32_t hi = f2tf32(v);
        int o = (bl * 128 + ic) * 40 + q0;
        shH[o] = hi;
        shL[o] = f2tf32(v - __uint_as_float(hi));
    }

    // --- warp tile: 32 rows x 32 oc ---
    int n0 = (wid & 1) * 32;
    int bl = wid >> 1;

    float acc[2][4][4];
#pragma unroll
    for (int mt = 0; mt < 2; mt++)
#pragma unroll
        for (int j = 0; j < 4; j++)
#pragma unroll
            for (int v = 0; v < 4; v++) acc[mt][j][v] = 0.f;

    for (int tap = 0; tap < 3; tap++) {
        for (int half = 0; half < 2; half++) {
            __syncthreads();
            for (int i = tid; i < 64 * 64; i += 256) {
                int icl = i >> 6, oc = i & 63;
                float wv = w2[(((half * 64 + icl) * 64) + oc) * 3 + (2 - tap)];
                uint32_t hi = f2tf32(wv);
                sBH[icl * 72 + oc] = hi;
                sBL[icl * 72 + oc] = f2tf32(wv - __uint_as_float(hi));
            }
            __syncthreads();
#pragma unroll 2
            for (int kk = 0; kk < 8; kk++) {
                int icg0 = half * 64 + kk * 8;
                uint32_t aH[2][4], aL[2][4];
#pragma unroll
                for (int mt = 0; mt < 2; mt++) {
                    int rb = bl * 5120 + mt * 16 + g + tap;
                    int o0 = rb + (icg0 + q) * 40;
                    int o1 = rb + (icg0 + q + 4) * 40;
                    aH[mt][0] = shH[o0];     aL[mt][0] = shL[o0];
                    aH[mt][1] = shH[o0 + 8]; aL[mt][1] = shL[o0 + 8];
                    aH[mt][2] = shH[o1];     aL[mt][2] = shL[o1];
                    aH[mt][3] = shH[o1 + 8]; aL[mt][3] = shL[o1 + 8];
                }
                uint32_t bH[4][2], bL[4][2];
                int kq = kk * 8 + q;
#pragma unroll
                for (int j = 0; j < 4; j++) {
                    int c0 = kq * 72 + n0 + 8 * j + g;
                    int c1 = (kq + 4) * 72 + n0 + 8 * j + g;
                    bH[j][0] = sBH[c0]; bH[j][1] = sBH[c1];
                    bL[j][0] = sBL[c0]; bL[j][1] = sBL[c1];
                }
#pragma unroll
                for (int mt = 0; mt < 2; mt++)
#pragma unroll
                    for (int j = 0; j < 4; j++) {
                        asm volatile(
                            "mma.sync.aligned.m16n8k8.row.col.f32.tf32.tf32.f32 "
                            "{%0,%1,%2,%3},{%4,%5,%6,%7},{%8,%9},{%0,%1,%2,%3};"
                            : "+f"(acc[mt][j][0]), "+f"(acc[mt][j][1]),
                              "+f"(acc[mt][j][2]), "+f"(acc[mt][j][3])
                            : "r"(aH[mt][0]), "r"(aH[mt][1]), "r"(aH[mt][2]), "r"(aH[mt][3]),
                              "r"(bL[j][0]), "r"(bL[j][1]));
                        asm volatile(
                            "mma.sync.aligned.m16n8k8.row.col.f32.tf32.tf32.f32 "
                            "{%0,%1,%2,%3},{%4,%5,%6,%7},{%8,%9},{%0,%1,%2,%3};"
                            : "+f"(acc[mt][j][0]), "+f"(acc[mt][j][1]),
                              "+f"(acc[mt][j][2]), "+f"(acc[mt][j][3])
                            : "r"(aL[mt][0]), "r"(aL[mt][1]), "r"(aL[mt][2]), "r"(aL[mt][3]),
                              "r"(bH[j][0]), "r"(bH[j][1]));
                        asm volatile(
                            "mma.sync.aligned.m16n8k8.row.col.f32.tf32.tf32.f32 "
                            "{%0,%1,%2,%3},{%4,%5,%6,%7},{%8,%9},{%0,%1,%2,%3};"
                            : "+f"(acc[mt][j][0]), "+f"(acc[mt][j][1]),
                              "+f"(acc[mt][j][2]), "+f"(acc[mt][j][3])
                            : "r"(aH[mt][0]), "r"(aH[mt][1]), "r"(aH[mt][2]), "r"(aH[mt][3]),
                              "r"(bH[j][0]), "r"(bH[j][1]));
                    }
            }
        }
    }

    // --- epilogue: bias + relu, store h2, per-oc stats ---
    int b = bbase + bl;
    float bias[4][2];
#pragma unroll
    for (int j = 0; j < 4; j++) {
        bias[j][0] = __ldg(&b2[n0 + 8 * j + 2 * q]);
        bias[j][1] = __ldg(&b2[n0 + 8 * j + 2 * q + 1]);
    }
    float ssum[4][2], ssq[4][2];
#pragma unroll
    for (int j = 0; j < 4; j++)
        for (int c = 0; c < 2; c++) { ssum[j][c] = 0.f; ssq[j][c] = 0.f; }

#pragma unroll
    for (int mt = 0; mt < 2; mt++)
#pragma unroll
        for (int j = 0; j < 4; j++)
#pragma unroll
            for (int h = 0; h < 2; h++)
#pragma unroll
                for (int c = 0; c < 2; c++) {
                    int oc = n0 + 8 * j + 2 * q + c;
                    int p = mt * 16 + h * 8 + g;
                    float y = fmaxf(acc[mt][j][h * 2 + c] + bias[j][c], 0.f);
                    g_h2[(b * 64 + oc) * 32 + p] = y;
                    ssum[j][c] += y;
                    ssq[j][c]  += y * y;
                }
#pragma unroll
    for (int j = 0; j < 4; j++)
#pragma unroll
        for (int c = 0; c < 2; c++) {
#pragma unroll
            for (int mk = 4; mk <= 16; mk <<= 1) {
                ssum[j][c] += __shfl_xor_sync(0xffffffffu, ssum[j][c], mk);
                ssq[j][c]  += __shfl_xor_sync(0xffffffffu, ssq[j][c], mk);
            }
        }
    if (lid < 4) {
#pragma unroll
        for (int j = 0; j < 4; j++)
#pragma unroll
            for (int c = 0; c < 2; c++) {
                int oc = n0 + 8 * j + 2 * lid + c;
                atomicAdd(&red[oc], ssum[j][c]);
                atomicAdd(&red[64 + oc], ssq[j][c]);
            }
    }
    __syncthreads();
    if (tid < 128) atomicAdd(&g_stats2[tid], (double)red[tid]);
}

// ------------------------------------------------------------------
__global__ void k_conv3(const float* __restrict__ w3, const float* __restrict__ b3,
                        float* __restrict__ out) {
    __shared__ float sa[64], sc[64], swv[192], sb3;
    int tid = threadIdx.x;
    if (tid < 64) { sa[tid] = g_a2[tid]; sc[tid] = g_c2[tid]; }
    if (tid < 192) swv[tid] = w3[tid];
    if (tid == 0) sb3 = b3[0];
    __syncthreads();

    int t = blockIdx.x * 256 + tid;
    int b = t >> 5, p = t & 31;
    const float* base = &g_h2[b * 64 * 32];
    float acc = sb3;
#pragma unroll 4
    for (int ic = 0; ic < 64; ic++) {
        const float* row = base + ic * 32;
        float a = sa[ic], cs = sc[ic];
        float x0 = fmaf(a, row[p], cs);
        float xm = (p > 0)  ? fmaf(a, row[p - 1], cs) : 0.f;
        float xp = (p < 31) ? fmaf(a, row[p + 1], cs) : 0.f;
        acc += xm * swv[ic * 3 + 2] + x0 * swv[ic * 3 + 1] + xp * swv[ic * 3 + 0];
    }
    out[t] = tanhf(acc);
}

// ------------------------------------------------------------------
extern "C" void kernel_launch(void* const* d_in, const int* in_sizes, int n_in,
                              void* d_out, int out_size) {
    const float* x   = (const float*)d_in[0];
    const float* qp  = (const float*)d_in[1];
    const float* w1  = (const float*)d_in[2];
    const float* b1  = (const float*)d_in[3];
    const float* g1  = (const float*)d_in[4];
    const float* be1 = (const float*)d_in[5];
    const float* w2  = (const float*)d_in[6];
    const float* b2  = (const float*)d_in[7];
    const float* g2  = (const float*)d_in[8];
    const float* be2 = (const float*)d_in[9];
    const float* w3  = (const float*)d_in[10];
    const float* b3  = (const float*)d_in[11];
    float* out = (float*)d_out;

    const int smem_bytes = SM_FLOATS * (int)sizeof(float);   // 204832 B
    cudaFuncSetAttribute(k_conv2, cudaFuncAttributeMaxDynamicSharedMemorySize, smem_bytes);

    k_zero_stats<<<1, 256>>>();
    k_images<<<(BSZ * 4) / 256, 256>>>(x, qp);
    k_conv1_stats<<<BSZ / CH2, 128>>>(w1, b1);
    k_fin1<<<1, 128>>>(g1, be1);
    k_conv2<<<BSZ / 4, 256, smem_bytes>>>(w1, b1, w2, b2);
    k_fin2<<<1, 64>>>(g2, be2);
    k_conv3<<<(BSZ * 32) / 256, 256>>>(w3, b3, out);
}

// round 6
// speedup vs baseline: 2.1299x; 2.1299x over previous
#include <cuda_runtime.h>
#include <cuda_bf16.h>
#include <math.h>
#include <stdint.h>

#define BSZ   16384
#define LSP   32
#define C1    128
#define C2    64
#define CH2   16

// ---- persistent device scratch ----
__device__ float  g_images[BSZ * LSP];
__device__ float  g_h2[BSZ * C2 * LSP];
__device__ double g_stats1[2 * C1];
__device__ double g_stats2[2 * C2];
__device__ float  g_a1[C1], g_c1[C1];
__device__ float  g_a2[C2], g_c2[C2];

// pack two floats as bf16x2: low 16 bits = `even`, high = `odd`
__device__ __forceinline__ uint32_t packbf(float even, float odd) {
    uint32_t r;
    asm("cvt.rn.bf16x2.f32 %0, %1, %2;" : "=r"(r) : "f"(odd), "f"(even));
    return r;
}
__device__ __forceinline__ float bf16f(float v) {
    return __bfloat162float(__float2bfloat16_rn(v));
}

// ================================================================
__global__ void k_zero_stats() {
    int t = threadIdx.x;
    if (t < 2 * C1) g_stats1[t] = 0.0;
    if (t < 2 * C2) g_stats2[t] = 0.0;
}

// ------------------------------------------------------------------
// given = probs[:8]/max(probs[:8]) (sum-normalization cancels).
__global__ void k_images(const float* __restrict__ x, const float* __restrict__ qp) {
    int t = blockIdx.x * blockDim.x + threadIdx.x;
    if (t >= BSZ * 4) return;
    int b = t >> 2, g = t & 3;
    float c[4], s[4];
#pragma unroll
    for (int q = 0; q < 4; q++) {
        float th = 0.5f * (x[b * 4 + q] + qp[g * 4 + q]);
        c[q] = cosf(th);
        s[q] = sinf(th);
    }
    float p[8];
    float mx = 0.f;
#pragma unroll
    for (int i = 0; i < 8; i++) {
        float a = c[0];
        a *= ((i >> 2) & 1) ? s[1] : c[1];
        a *= ((i >> 1) & 1) ? s[2] : c[2];
        a *= (i & 1)        ? s[3] : c[3];
        float pp = a * a;
        p[i] = pp;
        mx = fmaxf(mx, pp);
    }
    float inv = 1.0f / mx;
#pragma unroll
    for (int i = 0; i < 8; i++) g_images[b * 32 + g * 8 + i] = p[i] * inv;
}

// ------------------------------------------------------------------
__global__ void k_conv1_stats(const float* __restrict__ w1, const float* __restrict__ b1) {
    __shared__ float sh[CH2][34];
    int tid = threadIdx.x;
    int b0 = blockIdx.x * CH2;
    for (int i = tid; i < CH2 * 32; i += 128)
        sh[i >> 5][(i & 31) + 1] = g_images[(b0 + (i >> 5)) * 32 + (i & 31)];
    if (tid < CH2) { sh[tid][0] = 0.f; sh[tid][33] = 0.f; }
    __syncthreads();

    int oc = tid;
    float wA = w1[oc * 3 + 2], wB = w1[oc * 3 + 1], wC = w1[oc * 3 + 0], bb = b1[oc];
    float sum = 0.f, sq = 0.f;
    for (int r = 0; r < CH2; r++) {
#pragma unroll
        for (int p = 0; p < 32; p++) {
            float y = bb + sh[r][p] * wA + sh[r][p + 1] * wB + sh[r][p + 2] * wC;
            y = fmaxf(y, 0.f);
            sum += y;
            sq += y * y;
        }
    }
    atomicAdd(&g_stats1[oc], (double)sum);
    atomicAdd(&g_stats1[C1 + oc], (double)sq);
}

// ------------------------------------------------------------------
__global__ void k_fin1(const float* __restrict__ gamma, const float* __restrict__ beta) {
    int c = threadIdx.x;
    if (c >= C1) return;
    double N = (double)BSZ * LSP;
    double mean = g_stats1[c] / N;
    double var = g_stats1[C1 + c] / N - mean * mean;
    float a = gamma[c] * (float)(1.0 / sqrt(var + 1e-5));
    g_a1[c] = a;
    g_c1[c] = beta[c] - (float)mean * a;
}

__global__ void k_fin2(const float* __restrict__ gamma, const float* __restrict__ beta) {
    int c = threadIdx.x;
    if (c >= C2) return;
    double N = (double)BSZ * LSP;
    double mean = g_stats2[c] / N;
    double var = g_stats2[C2 + c] / N - mean * mean;
    float a = gamma[c] * (float)(1.0 / sqrt(var + 1e-5));
    g_a2[c] = a;
    g_c2[c] = beta[c] - (float)mean * a;
}

// ------------------------------------------------------------------
// conv2 via mma.sync bf16 (m16n8k16), 3-term bf16 split:
//   D = Ahi*Bhi + Alo*Bhi + Ahi*Blo   (alo*blo ~2^-18 dropped)
// Per CTA: 4 batch rows -> M=128 pos, N=64 oc, K=384 (3 taps x 128 ic).
// A smem: [bl][q0=pos+halo (0..33)][ic-pair], stride 68 words (4g+q banks).
// B smem (per tap): [k-pair][oc], stride 72 words (8q+g banks).
// sp/simg (pre-B) and red (post-B) overlay the B region.
#define OFF_AH 0          // 4*34*68 = 9248 words
#define OFF_AL 9248
#define OFF_B  18496      // B region: BH 4608 + BL 4608
#define OFF_BH 18496
#define OFF_BL 23104
#define SM_FLOATS 27712   // 110848 bytes

__global__ void __launch_bounds__(256, 2)
k_conv2(const float* __restrict__ w1, const float* __restrict__ b1,
        const float* __restrict__ w2, const float* __restrict__ b2) {
    extern __shared__ float sm[];
    uint32_t* sAH = (uint32_t*)(sm + OFF_AH);
    uint32_t* sAL = (uint32_t*)(sm + OFF_AL);
    uint32_t* sBH = (uint32_t*)(sm + OFF_BH);
    uint32_t* sBL = (uint32_t*)(sm + OFF_BL);
    float* sp   = sm + OFF_B;          // overlay, used only before B staging
    float* simg = sm + OFF_B + 768;
    float* red  = sm + OFF_B;          // overlay, used only after main loop

    int tid = threadIdx.x;
    int wid = tid >> 5, lid = tid & 31;
    int g = lid >> 2, q = lid & 3;
    int bbase = blockIdx.x * 4;

    // --- stage conv1 params + images (into B-region overlay) ---
    for (int i = tid; i < 128; i += 256) {
        sp[i * 6 + 0] = w1[i * 3 + 0];
        sp[i * 6 + 1] = w1[i * 3 + 1];
        sp[i * 6 + 2] = w1[i * 3 + 2];
        sp[i * 6 + 3] = b1[i];
        sp[i * 6 + 4] = g_a1[i];
        sp[i * 6 + 5] = g_c1[i];
    }
    for (int i = tid; i < 4 * 32; i += 256) {
        int bl = i >> 5, p = i & 31;
        simg[bl * 34 + p + 1] = g_images[(bbase + bl) * 32 + p];
    }
    if (tid < 4) { simg[tid * 34] = 0.f; simg[tid * 34 + 33] = 0.f; }
    __syncthreads();

    // --- h1n = a1*relu(conv1)+c1, split to bf16 hi/lo, packed ic-pairs ---
    for (int idx = tid; idx < 4 * 34 * 64; idx += 256) {
        int bl = idx / 2176, r = idx - bl * 2176;
        int q0 = r >> 6, u = r & 63;
        float v0 = 0.f, v1 = 0.f;
        if (q0 >= 1 && q0 <= 32) {
            int p = q0 - 1;
            float i0 = simg[bl * 34 + p], i1 = simg[bl * 34 + p + 1], i2 = simg[bl * 34 + p + 2];
            const float* p0 = &sp[(2 * u) * 6];
            float y0 = p0[3] + i0 * p0[2] + i1 * p0[1] + i2 * p0[0];
            v0 = fmaf(p0[4], fmaxf(y0, 0.f), p0[5]);
            const float* p1 = &sp[(2 * u + 1) * 6];
            float y1 = p1[3] + i0 * p1[2] + i1 * p1[1] + i2 * p1[0];
            v1 = fmaf(p1[4], fmaxf(y1, 0.f), p1[5]);
        }
        int o = (bl * 34 + q0) * 68 + u;
        sAH[o] = packbf(v0, v1);
        sAL[o] = packbf(v0 - bf16f(v0), v1 - bf16f(v1));
    }

    // --- warp tile: 32 rows (batch row bl) x 32 oc ---
    int bl = wid >> 1;
    int n0 = (wid & 1) * 32;

    float acc[2][4][4];
#pragma unroll
    for (int mt = 0; mt < 2; mt++)
#pragma unroll
        for (int j = 0; j < 4; j++)
#pragma unroll
            for (int v = 0; v < 4; v++) acc[mt][j][v] = 0.f;

    for (int tap = 0; tap < 3; tap++) {
        __syncthreads();
        // stage B(tap): word(kp, oc) packs ic = 2kp, 2kp+1
        for (int i = tid; i < 4096; i += 256) {
            int kp = i >> 6, oc = i & 63;
            float v0 = w2[((2 * kp) * 64 + oc) * 3 + (2 - tap)];
            float v1 = w2[((2 * kp + 1) * 64 + oc) * 3 + (2 - tap)];
            sBH[kp * 72 + oc] = packbf(v0, v1);
            sBL[kp * 72 + oc] = packbf(v0 - bf16f(v0), v1 - bf16f(v1));
        }
        __syncthreads();
#pragma unroll 2
        for (int kk = 0; kk < 8; kk++) {
            int kb2 = kk * 8;
            uint32_t AH[2][4], AL[2][4];
#pragma unroll
            for (int mt = 0; mt < 2; mt++) {
                int base = bl * 2312 + (mt * 16 + g + tap) * 68 + kb2 + q;
                AH[mt][0] = sAH[base];       AL[mt][0] = sAL[base];
                AH[mt][1] = sAH[base + 544]; AL[mt][1] = sAL[base + 544];
                AH[mt][2] = sAH[base + 4];   AL[mt][2] = sAL[base + 4];
                AH[mt][3] = sAH[base + 548]; AL[mt][3] = sAL[base + 548];
            }
            uint32_t BH[4][2], BL[4][2];
#pragma unroll
            for (int j = 0; j < 4; j++) {
                int n = n0 + 8 * j + g;
                int c0 = (kb2 + q) * 72 + n;
                int c1 = (kb2 + q + 4) * 72 + n;
                BH[j][0] = sBH[c0]; BH[j][1] = sBH[c1];
                BL[j][0] = sBL[c0]; BL[j][1] = sBL[c1];
            }
#pragma unroll
            for (int mt = 0; mt < 2; mt++)
#pragma unroll
                for (int j = 0; j < 4; j++) {
                    asm volatile(
                        "mma.sync.aligned.m16n8k16.row.col.f32.bf16.bf16.f32 "
                        "{%0,%1,%2,%3},{%4,%5,%6,%7},{%8,%9},{%0,%1,%2,%3};"
                        : "+f"(acc[mt][j][0]), "+f"(acc[mt][j][1]),
                          "+f"(acc[mt][j][2]), "+f"(acc[mt][j][3])
                        : "r"(AH[mt][0]), "r"(AH[mt][1]), "r"(AH[mt][2]), "r"(AH[mt][3]),
                          "r"(BL[j][0]), "r"(BL[j][1]));
                    asm volatile(
                        "mma.sync.aligned.m16n8k16.row.col.f32.bf16.bf16.f32 "
                        "{%0,%1,%2,%3},{%4,%5,%6,%7},{%8,%9},{%0,%1,%2,%3};"
                        : "+f"(acc[mt][j][0]), "+f"(acc[mt][j][1]),
                          "+f"(acc[mt][j][2]), "+f"(acc[mt][j][3])
                        : "r"(AL[mt][0]), "r"(AL[mt][1]), "r"(AL[mt][2]), "r"(AL[mt][3]),
                          "r"(BH[j][0]), "r"(BH[j][1]));
                    asm volatile(
                        "mma.sync.aligned.m16n8k16.row.col.f32.bf16.bf16.f32 "
                        "{%0,%1,%2,%3},{%4,%5,%6,%7},{%8,%9},{%0,%1,%2,%3};"
                        : "+f"(acc[mt][j][0]), "+f"(acc[mt][j][1]),
                          "+f"(acc[mt][j][2]), "+f"(acc[mt][j][3])
                        : "r"(AH[mt][0]), "r"(AH[mt][1]), "r"(AH[mt][2]), "r"(AH[mt][3]),
                          "r"(BH[j][0]), "r"(BH[j][1]));
                }
        }
    }

    // --- epilogue: bias + relu, store h2, per-oc stats ---
    __syncthreads();
    if (tid < 128) red[tid] = 0.f;
    __syncthreads();

    int b = bbase + bl;
    float bias[4][2];
#pragma unroll
    for (int j = 0; j < 4; j++) {
        bias[j][0] = __ldg(&b2[n0 + 8 * j + 2 * q]);
        bias[j][1] = __ldg(&b2[n0 + 8 * j + 2 * q + 1]);
    }
    float ssum[4][2], ssq[4][2];
#pragma unroll
    for (int j = 0; j < 4; j++)
        for (int c = 0; c < 2; c++) { ssum[j][c] = 0.f; ssq[j][c] = 0.f; }

#pragma unroll
    for (int mt = 0; mt < 2; mt++)
#pragma unroll
        for (int j = 0; j < 4; j++)
#pragma unroll
            for (int h = 0; h < 2; h++)
#pragma unroll
                for (int c = 0; c < 2; c++) {
                    int oc = n0 + 8 * j + 2 * q + c;
                    int p = mt * 16 + h * 8 + g;
                    float y = fmaxf(acc[mt][j][h * 2 + c] + bias[j][c], 0.f);
                    g_h2[(b * 64 + oc) * 32 + p] = y;
                    ssum[j][c] += y;
                    ssq[j][c]  += y * y;
                }
#pragma unroll
    for (int j = 0; j < 4; j++)
#pragma unroll
        for (int c = 0; c < 2; c++) {
#pragma unroll
            for (int mk = 4; mk <= 16; mk <<= 1) {
                ssum[j][c] += __shfl_xor_sync(0xffffffffu, ssum[j][c], mk);
                ssq[j][c]  += __shfl_xor_sync(0xffffffffu, ssq[j][c], mk);
            }
        }
    if (lid < 4) {
#pragma unroll
        for (int j = 0; j < 4; j++)
#pragma unroll
            for (int c = 0; c < 2; c++) {
                int oc = n0 + 8 * j + 2 * lid + c;
                atomicAdd(&red[oc], ssum[j][c]);
                atomicAdd(&red[64 + oc], ssq[j][c]);
            }
    }
    __syncthreads();
    if (tid < 128) atomicAdd(&g_stats2[tid], (double)red[tid]);
}

// ------------------------------------------------------------------
__global__ void k_conv3(const float* __restrict__ w3, const float* __restrict__ b3,
                        float* __restrict__ out) {
    __shared__ float sa[64], sc[64], swv[192], sb3;
    int tid = threadIdx.x;
    if (tid < 64) { sa[tid] = g_a2[tid]; sc[tid] = g_c2[tid]; }
    if (tid < 192) swv[tid] = w3[tid];
    if (tid == 0) sb3 = b3[0];
    __syncthreads();

    int t = blockIdx.x * 256 + tid;
    int b = t >> 5, p = t & 31;
    const float* base = &g_h2[b * 64 * 32];
    float acc = sb3;
#pragma unroll 4
    for (int ic = 0; ic < 64; ic++) {
        const float* row = base + ic * 32;
        float a = sa[ic], cs = sc[ic];
        float x0 = fmaf(a, row[p], cs);
        float xm = (p > 0)  ? fmaf(a, row[p - 1], cs) : 0.f;
        float xp = (p < 31) ? fmaf(a, row[p + 1], cs) : 0.f;
        acc += xm * swv[ic * 3 + 2] + x0 * swv[ic * 3 + 1] + xp * swv[ic * 3 + 0];
    }
    out[t] = tanhf(acc);
}

// ------------------------------------------------------------------
extern "C" void kernel_launch(void* const* d_in, const int* in_sizes, int n_in,
                              void* d_out, int out_size) {
    const float* x   = (const float*)d_in[0];
    const float* qp  = (const float*)d_in[1];
    const float* w1  = (const float*)d_in[2];
    const float* b1  = (const float*)d_in[3];
    const float* g1  = (const float*)d_in[4];
    const float* be1 = (const float*)d_in[5];
    const float* w2  = (const float*)d_in[6];
    const float* b2  = (const float*)d_in[7];
    const float* g2  = (const float*)d_in[8];
    const float* be2 = (const float*)d_in[9];
    const float* w3  = (const float*)d_in[10];
    const float* b3  = (const float*)d_in[11];
    float* out = (float*)d_out;

    const int smem_bytes = SM_FLOATS * (int)sizeof(float);   // 110848 B
    cudaFuncSetAttribute(k_conv2, cudaFuncAttributeMaxDynamicSharedMemorySize, smem_bytes);

    k_zero_stats<<<1, 256>>>();
    k_images<<<(BSZ * 4) / 256, 256>>>(x, qp);
    k_conv1_stats<<<BSZ / CH2, 128>>>(w1, b1);
    k_fin1<<<1, 128>>>(g1, be1);
    k_conv2<<<BSZ / 4, 256, smem_bytes>>>(w1, b1, w2, b2);
    k_fin2<<<1, 64>>>(g2, be2);
    k_conv3<<<(BSZ * 32) / 256, 256>>>(w3, b3, out);
}